// round 14
// baseline (speedup 1.0000x reference)
#include <cuda_runtime.h>

// Soft-DTW (gamma=1), 64 batches of 1024x1024, one CTA per batch.
// Warp-skewed block pipeline (KB=16 diags/block), 8 warps x 32 lanes,
// 4 contiguous rows per thread (rows 128*wid + 4*lane .. +3).
// One __syncthreads per superstep (135 total). Triangular block skip.
// Log2-domain softmin (2 ex2 + 1 lg2 per cell), dot-form distances,
// sentinel-padded contour (no per-iter clamps), sliding 4-point contour
// window in registers (1 LDS.128 per 4 cells).

#define NBATCH 64
#define NPTS   1024
#define TPB    256
#define NW     8
#define KB     16
#define NBLK   128                    // block 127 holds 15 diags (2032..2046)
#define NSUP   (NBLK + NW - 1)
#define BIGV   1.0e30f
#define SENT   1.0e17f
#define LN2F   0.69314718055994531f
#define PAD    128
#define SCPN   1280                   // indices used: [2, 1279]

__device__ float g_partial[NBATCH];

__device__ __forceinline__ float ex2f(float x) {
    float r; asm("ex2.approx.ftz.f32 %0, %1;" : "=f"(r) : "f"(x)); return r;
}
__device__ __forceinline__ float lg2f(float x) {
    float r; asm("lg2.approx.ftz.f32 %0, %1;" : "=f"(r) : "f"(x)); return r;
}

// softmin in log2 domain: one exp arg is always 0 -> 2 ex2 + 1 lg2.
__device__ __forceinline__ float cellv(float a, float bq, float c, float Dl) {
    float t1  = fminf(a, bq);
    float t2  = fmaxf(a, bq);
    float mn  = fminf(t1, c);
    float mx  = fmaxf(t2, c);
    float mid = fminf(t2, fmaxf(t1, c));
    float s   = 1.0f + (ex2f(mn - mid) + ex2f(mn - mx));
    return Dl + (mn - lg2f(s));
}

typedef float BufT[2][NW][KB + 1];

struct RowC { float m2x, m2y, s2; };   // dot-form per-row constants

__device__ __forceinline__ float distf(const RowC& rc, const float4& c) {
    return fmaf(rc.m2y, c.y, fmaf(rc.m2x, c.x, rc.s2 + c.z));
}

template<int KMAX>
__device__ __forceinline__ void run_block(
    BufT& bufk, int slot, int wid, int lane,
    const float4* pc, float4& c1, float4& c2, float4& c3,
    float& cur_a, float& cur_b, float& cur_c, float& cur_d,
    float& old_a, float& old_b, float& old_c, float& nb2,
    const RowC& ra, const RowC& rb, const RowC& rc, const RowC& rd)
{
    #pragma unroll
    for (int k = 0; k < KMAX; ++k) {
        float nb1 = __shfl_up_sync(0xFFFFFFFFu, cur_d, 1);
        if (lane == 0) nb1 = (wid == 0) ? BIGV : bufk[slot][wid - 1][k];

        float4 ca = pc[k];
        float Dla = distf(ra, ca);
        float Dlb = distf(rb, c1);
        float Dlc = distf(rc, c2);
        float Dld = distf(rd, c3);

        float new_a = cellv(nb2,   nb1,   cur_a, Dla);
        float new_b = cellv(old_a, cur_a, cur_b, Dlb);
        float new_c = cellv(old_b, cur_b, cur_c, Dlc);
        float new_d = cellv(old_c, cur_c, cur_d, Dld);

        if (lane == 31) bufk[slot][wid][k + 1] = new_d;

        nb2 = nb1;
        old_a = cur_a; old_b = cur_b; old_c = cur_c;
        cur_a = new_a; cur_b = new_b; cur_c = new_c; cur_d = new_d;
        c3 = c2; c2 = c1; c1 = ca;
    }
}

__global__ __launch_bounds__(TPB, 1)
void dtw_kernel(const float* __restrict__ snake, const float* __restrict__ contour)
{
    __shared__ float4 scp[SCPN];      // (cx, cy, cx^2+cy^2, 0), sentinel outside
    __shared__ BufT   bufk;           // strip: [slot][warp][0=carry,1..16]

    const int tid  = threadIdx.x;
    const int lane = tid & 31;
    const int wid  = tid >> 5;
    const int b    = blockIdx.x;
    const float SCALE = 1.2011224087864498f;   // sqrt(log2 e)

    // scp[idx] <-> jp = idx - PAD; valid contour at jp in [1,1024].
    for (int k = tid; k < SCPN; k += TPB) {
        int j = k - PAD;
        float cx = SENT, cy = SENT;
        if (j >= 1 && j <= NPTS) {
            float2 c = ((const float2*)contour)[b * NPTS + j - 1];
            cx = c.x * SCALE; cy = c.y * SCALE;
        }
        scp[k] = make_float4(cx, cy, fmaf(cx, cx, cy * cy), 0.f);
    }
    for (int k = tid; k < 2 * NW * (KB + 1); k += TPB)
        ((float*)bufk)[k] = BIGV;

    // This thread's 4 rows: base .. base+3.
    const int base = wid * 128 + lane * 4;
    float4 s01 = ((const float4*)snake)[(b * NPTS + base) >> 1];
    float4 s23 = ((const float4*)snake)[((b * NPTS + base) >> 1) + 1];
    RowC ra, rb, rc, rd;
    {
        float x, y;
        x = s01.x * SCALE; y = s01.y * SCALE;
        ra.m2x = -2.f * x; ra.m2y = -2.f * y; ra.s2 = fmaf(x, x, y * y);
        x = s01.z * SCALE; y = s01.w * SCALE;
        rb.m2x = -2.f * x; rb.m2y = -2.f * y; rb.s2 = fmaf(x, x, y * y);
        x = s23.x * SCALE; y = s23.y * SCALE;
        rc.m2x = -2.f * x; rc.m2y = -2.f * y; rc.s2 = fmaf(x, x, y * y);
        x = s23.z * SCALE; y = s23.w * SCALE;
        rd.m2x = -2.f * x; rd.m2y = -2.f * y; rd.s2 = fmaf(x, x, y * y);
    }

    __syncthreads();

    float cur_a = BIGV, cur_b = BIGV, cur_c = BIGV, cur_d = BIGV;
    float old_a = BIGV, old_b = BIGV, old_c = BIGV, nb2 = BIGV;
    if (tid == 0) nb2 = 0.0f;         // R(-1,-1)=0 => cell(0,0)=D(0,0)

    const int tLo = 8 * wid;          // first block touching row 128*wid
    const int tHi = min(NBLK - 1, 8 * wid + 71);

    const int jp0 = tLo * KB - base + 1;   // jp of row a at first active diag
    const float4* pc = &scp[jp0 + PAD];
    float4 c1 = pc[-1], c2 = pc[-2], c3 = pc[-3];

    for (int s = 0; s < NSUP; ++s) {
        const int t = s - wid;
        if (t >= tLo && t <= tHi) {
            const int slot = t & 1;
            if (lane == 31) bufk[slot][wid][0] = cur_d;   // carry: diag tKB-1
            if (t < NBLK - 1) {
                run_block<16>(bufk, slot, wid, lane, pc, c1, c2, c3,
                              cur_a, cur_b, cur_c, cur_d,
                              old_a, old_b, old_c, nb2, ra, rb, rc, rd);
                pc += 16;
            } else {
                run_block<15>(bufk, slot, wid, lane, pc, c1, c2, c3,
                              cur_a, cur_b, cur_c, cur_d,
                              old_a, old_b, old_c, nb2, ra, rb, rc, rd);
                pc += 15;
            }
        }
        __syncthreads();
    }

    // Row 1023 = warp 7, lane 31, row d; value at diag 2046.
    if (tid == TPB - 1)
        g_partial[b] = cur_d * LN2F;  // log2 -> ln
}

__global__ void reduce_kernel(float* __restrict__ out)
{
    float v = g_partial[threadIdx.x] + g_partial[threadIdx.x + 32];
    #pragma unroll
    for (int off = 16; off > 0; off >>= 1)
        v += __shfl_down_sync(0xFFFFFFFFu, v, off);
    if (threadIdx.x == 0)
        out[0] = v * (1.0f / NBATCH);
}

extern "C" void kernel_launch(void* const* d_in, const int* in_sizes, int n_in,
                              void* d_out, int out_size)
{
    const float* snake   = (const float*)d_in[0];
    const float* contour = (const float*)d_in[1];
    float* out = (float*)d_out;

    dtw_kernel<<<NBATCH, TPB>>>(snake, contour);
    reduce_kernel<<<1, 32>>>(out);
}

// round 15
// speedup vs baseline: 1.9610x; 1.9610x over previous
#include <cuda_runtime.h>

// Soft-DTW (gamma=1), 64 batches of 1024x1024.
// FORWARD/BACKWARD SPLIT: every monotone path crosses the middle anti-diagonal
// once => R = softmin over cut terms combining a forward DP (diags 0..1023)
// and a backward DP (= forward DP on reversed sequences, diags 0..1023).
// 128 CTAs (64 fwd + 64 rev), each runs the proven R12 warp-skewed block
// pipeline (KB=16, 16 warps, 2 rows/thread, one __syncthreads/superstep,
// triangular skip, log2-domain softmin 2ex2+1lg2, dot-form distances,
// sentinel-padded contour) truncated at block 63, then dumps its diag-1022
// and diag-1023 values. A combine kernel does the exact cut softmin:
//   term_A(i) = F1023[i] + B1023'[i] - D(i,1023-i)          (cell on diag 1023)
//   term_B(i) = F1022[i] + B1022'[i]                        (diag jump 1022->1024)
// where B' arrays are the reversed DP's diag values (row-reversed indexing).

#define NBATCH 64
#define NPTS   1024
#define TPB    256            // combine kernel block
#define DTPB   512
#define NW     16
#define KB     16
#define NBLK   64             // diagonals 0..1023 only
#define NSUP   (NBLK + NW - 1)
#define BIGV   1.0e30f
#define SENT   1.0e17f
#define LN2F   0.69314718055994531f
#define PAD    64
#define SCPN   1100           // scp indices used: [1, 1088]

__device__ float g_partial[NBATCH];
__device__ float g_cut[NBATCH][4][NPTS];   // 0=f1022, 1=f1023, 2=r1022, 3=r1023

__device__ __forceinline__ float ex2f(float x) {
    float r; asm("ex2.approx.ftz.f32 %0, %1;" : "=f"(r) : "f"(x)); return r;
}
__device__ __forceinline__ float lg2f(float x) {
    float r; asm("lg2.approx.ftz.f32 %0, %1;" : "=f"(r) : "f"(x)); return r;
}

// softmin in log2 domain: one exp arg is always 0 -> 2 ex2 + 1 lg2.
__device__ __forceinline__ float cellv(float a, float bq, float c, float Dl) {
    float t1  = fminf(a, bq);
    float t2  = fmaxf(a, bq);
    float mn  = fminf(t1, c);
    float mx  = fmaxf(t2, c);
    float mid = fminf(t2, fmaxf(t1, c));
    float s   = 1.0f + (ex2f(mn - mid) + ex2f(mn - mx));
    return Dl + (mn - lg2f(s));
}

typedef float BufT[2][NW][KB + 1];

template<bool LAST>
__device__ __forceinline__ void run_block16(
    BufT& bufk, int slot, int wid, int lane,
    const float4* pc, float4& cb,
    float& cur_a, float& cur_b, float& cur_a_old, float& nb2,
    float m2ax, float m2ay, float s2a,
    float m2bx, float m2by, float s2b,
    float& o22a, float& o22b)
{
    #pragma unroll
    for (int k = 0; k < KB; ++k) {
        float nb1 = __shfl_up_sync(0xFFFFFFFFu, cur_b, 1);
        if (lane == 0) nb1 = (wid == 0) ? BIGV : bufk[slot][wid - 1][k];

        float4 ca = pc[k];
        float Dla = fmaf(m2ay, ca.y, fmaf(m2ax, ca.x, s2a + ca.z));
        float Dlb = fmaf(m2by, cb.y, fmaf(m2bx, cb.x, s2b + cb.z));

        float new_a = cellv(nb2,       nb1,   cur_a, Dla);
        float new_b = cellv(cur_a_old, cur_a, cur_b, Dlb);

        if (lane == 31) bufk[slot][wid][k + 1] = new_b;

        nb2 = nb1; cur_a_old = cur_a; cur_a = new_a; cur_b = new_b;
        cb = ca;
        if (LAST && k == KB - 2) { o22a = cur_a; o22b = cur_b; }  // diag 1022
    }
}

__global__ __launch_bounds__(DTPB, 1)
void dtw_kernel(const float* __restrict__ snake, const float* __restrict__ contour)
{
    __shared__ float4 scp[SCPN];      // (cx, cy, cx^2+cy^2, 0), sentinel outside
    __shared__ BufT   bufk;

    const int tid  = threadIdx.x;
    const int lane = tid & 31;
    const int wid  = tid >> 5;
    const int rev  = blockIdx.x & 1;  // 0 = forward, 1 = reversed sequences
    const int b    = blockIdx.x >> 1;
    const float SCALE = 1.2011224087864498f;   // sqrt(log2 e)

    // scp[idx] <-> jp = idx - PAD; valid contour at jp in [1,1024].
    // Reversed CTA uses contour[1024 - jp].
    for (int k = tid; k < SCPN; k += DTPB) {
        int j = k - PAD;
        float cx = SENT, cy = SENT;
        if (j >= 1 && j <= NPTS) {
            int src = rev ? (NPTS - j) : (j - 1);
            float2 c = ((const float2*)contour)[b * NPTS + src];
            cx = c.x * SCALE; cy = c.y * SCALE;
        }
        scp[k] = make_float4(cx, cy, fmaf(cx, cx, cy * cy), 0.f);
    }
    for (int k = tid; k < 2 * NW * (KB + 1); k += DTPB)
        ((float*)bufk)[k] = BIGV;

    // Rows 2*tid, 2*tid+1 (in this CTA's orientation).
    const int row_a = 2 * tid;
    float sax, say, sbx, sby;
    if (!rev) {
        float4 s4 = ((const float4*)snake)[b * DTPB + tid];
        sax = s4.x * SCALE; say = s4.y * SCALE;
        sbx = s4.z * SCALE; sby = s4.w * SCALE;
    } else {
        // rev rows 2tid,2tid+1 = orig rows 1023-2tid, 1022-2tid
        float4 s4 = ((const float4*)snake)[b * DTPB + (DTPB - 1 - tid)];
        sax = s4.z * SCALE; say = s4.w * SCALE;   // orig row 1023-2tid
        sbx = s4.x * SCALE; sby = s4.y * SCALE;   // orig row 1022-2tid
    }
    const float m2ax = -2.f * sax, m2ay = -2.f * say;
    const float s2a  = fmaf(sax, sax, say * say);
    const float m2bx = -2.f * sbx, m2by = -2.f * sby;
    const float s2b  = fmaf(sbx, sbx, sby * sby);

    __syncthreads();

    float cur_a = BIGV, cur_b = BIGV, cur_a_old = BIGV, nb2 = BIGV;
    if (tid == 0) nb2 = 0.0f;         // R(-1,-1)=0 => cell(0,0)=D(0,0)

    const int tLo = 4 * wid;          // blocks [4*wid, 63]
    const int jp0 = tLo * KB - row_a + 1;
    const float4* pc = &scp[jp0 + PAD];
    float4 cb = pc[-1];
    float o22a = BIGV, o22b = BIGV;

    for (int s = 0; s < NSUP; ++s) {
        const int t = s - wid;
        if (t >= tLo && t < NBLK) {
            const int slot = t & 1;
            if (lane == 31) bufk[slot][wid][0] = cur_b;   // carry: diag tKB-1
            if (t < NBLK - 1) {
                run_block16<false>(bufk, slot, wid, lane, pc, cb,
                                   cur_a, cur_b, cur_a_old, nb2,
                                   m2ax, m2ay, s2a, m2bx, m2by, s2b, o22a, o22b);
            } else {
                run_block16<true>(bufk, slot, wid, lane, pc, cb,
                                  cur_a, cur_b, cur_a_old, nb2,
                                  m2ax, m2ay, s2a, m2bx, m2by, s2b, o22a, o22b);
                // After block 63: cur_* = diag-1023 values, o22* = diag-1022.
                g_cut[b][2 * rev + 0][row_a]     = o22a;
                g_cut[b][2 * rev + 0][row_a + 1] = o22b;
                g_cut[b][2 * rev + 1][row_a]     = cur_a;
                g_cut[b][2 * rev + 1][row_a + 1] = cur_b;
            }
            pc += KB;
        }
        __syncthreads();
    }
}

__global__ __launch_bounds__(TPB)
void combine_kernel(const float* __restrict__ snake, const float* __restrict__ contour)
{
    __shared__ float red[64];
    const int b   = blockIdx.x;
    const int tid = threadIdx.x;
    const int lane = tid & 31, wid = tid >> 5;
    const float LOG2E = 1.4426950408889634f;

    float t[8];
    #pragma unroll
    for (int q = 0; q < 8; ++q) t[q] = BIGV;

    #pragma unroll
    for (int q = 0; q < 4; ++q) {
        int i = tid + q * TPB;                       // 0..1023
        float2 s = ((const float2*)snake)[b * NPTS + i];
        float2 c = ((const float2*)contour)[b * NPTS + (NPTS - 1 - i)];
        float dx = s.x - c.x, dy = s.y - c.y;
        float Dl = LOG2E * fmaf(dy, dy, dx * dx);
        // B'1023 at cell (i,1023-i) = rev DP diag-1023 at rev row 1023-i
        t[q] = g_cut[b][1][i] + g_cut[b][3][NPTS - 1 - i] - Dl;
    }
    #pragma unroll
    for (int q = 0; q < 4; ++q) {
        int i = tid + q * TPB;
        if (i < NPTS - 1)                            // 0..1022
            // B' at (i+1,1023-i) (diag 1024) = rev DP diag-1022 at rev row 1022-i
            t[4 + q] = g_cut[b][0][i] + g_cut[b][2][NPTS - 2 - i];
    }

    // Block min.
    float m = t[0];
    #pragma unroll
    for (int q = 1; q < 8; ++q) m = fminf(m, t[q]);
    #pragma unroll
    for (int off = 16; off > 0; off >>= 1)
        m = fminf(m, __shfl_xor_sync(0xFFFFFFFFu, m, off));
    if (lane == 0) red[wid] = m;
    __syncthreads();
    if (tid == 0) {
        float mm = red[0];
        for (int w = 1; w < TPB / 32; ++w) mm = fminf(mm, red[w]);
        red[0] = mm;
    }
    __syncthreads();
    m = red[0];

    // Sum of 2^(m - t).
    float S = 0.f;
    #pragma unroll
    for (int q = 0; q < 8; ++q) S += ex2f(m - t[q]);
    #pragma unroll
    for (int off = 16; off > 0; off >>= 1)
        S += __shfl_xor_sync(0xFFFFFFFFu, S, off);
    if (lane == 0) red[32 + wid] = S;
    __syncthreads();
    if (tid == 0) {
        float ss = 0.f;
        for (int w = 0; w < TPB / 32; ++w) ss += red[32 + w];
        g_partial[b] = (m - lg2f(ss)) * LN2F;        // softmin -> ln units
    }
}

__global__ void reduce_kernel(float* __restrict__ out)
{
    float v = g_partial[threadIdx.x] + g_partial[threadIdx.x + 32];
    #pragma unroll
    for (int off = 16; off > 0; off >>= 1)
        v += __shfl_down_sync(0xFFFFFFFFu, v, off);
    if (threadIdx.x == 0)
        out[0] = v * (1.0f / NBATCH);
}

extern "C" void kernel_launch(void* const* d_in, const int* in_sizes, int n_in,
                              void* d_out, int out_size)
{
    const float* snake   = (const float*)d_in[0];
    const float* contour = (const float*)d_in[1];
    float* out = (float*)d_out;

    dtw_kernel<<<NBATCH * 2, DTPB>>>(snake, contour);
    combine_kernel<<<NBATCH, TPB>>>(snake, contour);
    reduce_kernel<<<1, 32>>>(out);
}